// round 5
// baseline (speedup 1.0000x reference)
#include <cuda_runtime.h>
#include <cstdint>
#include <math.h>

// ---------------------------------------------------------------------------
// TransNetSweeping on GB300 — fused fp32, async weights, 8-row warps (R4).
//
// Math: A_l = [[I, aW],[-aW^T, cI]], a=0.1, c=11.
//   S = I + (a^2/c) W W^T,  M = S^{-1},  N = (a/c) M W
//   u = M p - N q ;  v = (q + a W^T u)/c
//   p = a*b_l + carry_u ; q = 10*tanh(z_l_u) + carry_v
// Fixed 15 Gauss-Seidel sweeps.
//
// k_sweep: 128 CTAs x 256 thr. Warp = 8 rows x 32 cols (lane owns one col).
// Weight loads are LDS.32 held in regs across 8 rows. Next-step q is fused
// into the v-epilogue (v still in registers). Weights stream via
// cp.async.bulk double buffer (2x32KB), flat 722-chunk sequence.
// ---------------------------------------------------------------------------

#define BATCH    2048
#define U        128
#define NLAYERS  8
#define NSTEPS   15

#define DT_A     0.1f
#define INVC     (1.0f/11.0f)
#define TANHK    10.0f

#define NCHUNKS  (NSTEPS * NLAYERS * 6 + 2)   // 722

__device__ float g_zin[BATCH * 256];
__device__ float g_Mt [NLAYERS * U * U];      // Mt[l][k][j] = M[j][k]
__device__ float g_Nt [NLAYERS * U * U];      // Nt[l][k][j] = N[j][k]
__device__ float g_WT [U * U];                // WT[i][k] = W7[k][i]

__device__ __forceinline__ float4 ld4(const float* p) { return *(const float4*)p; }
__device__ __forceinline__ void   st4(float* p, float4 v) { *(float4*)p = v; }
#define FC(v,t) (((const float*)&(v))[t])

__device__ __forceinline__ uint32_t s2u(const void* p) {
    uint32_t a;
    asm("{ .reg .u64 t; cvta.to.shared.u64 t, %1; cvt.u32.u64 %0, t; }" : "=r"(a) : "l"(p));
    return a;
}
__device__ __forceinline__ void mbar_init(uint32_t m, uint32_t cnt) {
    asm volatile("mbarrier.init.shared.b64 [%0], %1;" :: "r"(m), "r"(cnt) : "memory");
}
__device__ __forceinline__ void mbar_expect(uint32_t m, uint32_t tx) {
    asm volatile("mbarrier.arrive.expect_tx.shared.b64 _, [%0], %1;" :: "r"(m), "r"(tx) : "memory");
}
__device__ __forceinline__ void bulk_g2s(uint32_t dst, const void* src, uint32_t bytes, uint32_t m) {
    asm volatile("cp.async.bulk.shared::cluster.global.mbarrier::complete_tx::bytes [%0], [%1], %2, [%3];"
                 :: "r"(dst), "l"(src), "r"(bytes), "r"(m) : "memory");
}
__device__ __forceinline__ void mbar_wait(uint32_t m, uint32_t phase) {
    uint32_t done;
    do {
        asm volatile("{\n\t.reg .pred p;\n\t"
                     "mbarrier.try_wait.parity.acquire.cta.shared::cta.b64 p, [%1], %2, 0x989680;\n\t"
                     "selp.b32 %0, 1, 0, p;\n\t}"
                     : "=r"(done) : "r"(m), "r"(phase) : "memory");
    } while (!done);
}

// ---------------------------------------------------------------------------
// k_pre: merged prep (CTAs 0..7) + input projection (CTAs 8..135). Block 256.
// ---------------------------------------------------------------------------
#define WS_S 129
#define AS_S 260
#define PREP_SMEM ((128*WS_S + 128*AS_S + 128) * 4)

__device__ void prep_body(float* sm, const float* __restrict__ wblocks, int l)
{
    float* Wsh  = sm;
    float* aug  = sm + 128 * WS_S;
    float* colb = aug + 128 * AS_S;
    const int tid = threadIdx.x;
    const float* Wg = wblocks + l * U * U;

    for (int idx = tid; idx < U * U; idx += 256)
        Wsh[(idx >> 7) * WS_S + (idx & 127)] = Wg[idx];
    __syncthreads();

    const float kscl = (DT_A * DT_A) * INVC;
#pragma unroll 1
    for (int rep = 0; rep < 2; rep++) {
        const int pos = tid + rep * 256;
        const int ti = pos >> 4, tj = pos & 15;
        float acc[4][8];
#pragma unroll
        for (int r = 0; r < 4; r++)
#pragma unroll
            for (int j = 0; j < 8; j++) acc[r][j] = 0.f;
        for (int k = 0; k < U; k++) {
            float wi[4], wj[8];
#pragma unroll
            for (int r = 0; r < 4; r++) wi[r] = Wsh[(ti*4 + r) * WS_S + k];
#pragma unroll
            for (int j = 0; j < 8; j++) wj[j] = Wsh[(tj*8 + j) * WS_S + k];
#pragma unroll
            for (int r = 0; r < 4; r++)
#pragma unroll
                for (int j = 0; j < 8; j++) acc[r][j] += wi[r] * wj[j];
        }
#pragma unroll
        for (int r = 0; r < 4; r++)
#pragma unroll
            for (int j = 0; j < 8; j++) {
                int i = ti*4 + r, jj = tj*8 + j;
                aug[i * AS_S + jj] = kscl * acc[r][j] + (i == jj ? 1.f : 0.f);
            }
    }
    for (int idx = tid; idx < U * U; idx += 256) {
        int i = idx >> 7, j = idx & 127;
        aug[i * AS_S + 128 + j] = (i == j) ? 1.f : 0.f;
    }

    const int f4c = tid & 63, rgp = tid >> 6;
    for (int p = 0; p < U; p++) {
        __syncthreads();
        const float inv = 1.0f / aug[p * AS_S + p];
        if (tid < 128 && tid != p) colb[tid] = aug[tid * AS_S + p];
        __syncthreads();
        aug[p * AS_S + tid] *= inv;
        __syncthreads();
        const float4 rp = ld4(&aug[p * AS_S + f4c * 4]);
        for (int i = rgp * 32; i < rgp * 32 + 32; i++) {
            if (i == p) continue;
            const float fac = colb[i];
            float4 a = ld4(&aug[i * AS_S + f4c * 4]);
            a.x -= fac * rp.x; a.y -= fac * rp.y;
            a.z -= fac * rp.z; a.w -= fac * rp.w;
            st4(&aug[i * AS_S + f4c * 4], a);
        }
    }
    __syncthreads();

    // aug_left[m][j] := M[j][m]
    for (int idx = tid; idx < U * U; idx += 256) {
        int m = idx >> 7, j = idx & 127;
        aug[m * AS_S + j] = aug[j * AS_S + 128 + m];
    }
    __syncthreads();

    for (int idx = tid; idx < U * U; idx += 256) {
        int k = idx >> 7, j = idx & 127;
        g_Mt[l * U * U + idx] = aug[k * AS_S + j];
    }

    const float ac = DT_A * INVC;
#pragma unroll 1
    for (int rep = 0; rep < 2; rep++) {
        const int pos = tid + rep * 256;
        const int tk = pos >> 4, tj = pos & 15;
        float acc[4][8];
#pragma unroll
        for (int r = 0; r < 4; r++)
#pragma unroll
            for (int j = 0; j < 8; j++) acc[r][j] = 0.f;
        for (int m = 0; m < U; m++) {
            float wv[4], mv[8];
#pragma unroll
            for (int r = 0; r < 4; r++) wv[r] = Wsh[m * WS_S + tk*4 + r];
#pragma unroll
            for (int j = 0; j < 8; j++) mv[j] = aug[m * AS_S + tj*8 + j];
#pragma unroll
            for (int r = 0; r < 4; r++)
#pragma unroll
                for (int j = 0; j < 8; j++) acc[r][j] += wv[r] * mv[j];
        }
#pragma unroll
        for (int r = 0; r < 4; r++)
#pragma unroll
            for (int j = 0; j < 8; j++)
                g_Nt[l * U * U + (tk*4 + r) * U + tj*8 + j] = ac * acc[r][j];
    }

    if (l == NLAYERS - 1) {
        for (int idx = tid; idx < U * U; idx += 256) {
            int i = idx >> 7, j = idx & 127;
            g_WT[i * U + j] = Wsh[j * WS_S + i];
        }
    }
}

__device__ void input_body(float* sm, const float* __restrict__ x,
                           const float* __restrict__ win,
                           const float* __restrict__ bin, int bid)
{
    float* ws = sm;            // [16][132]
    float* xs = sm + 16 * 132; // [16][20]
    const int tid = threadIdx.x;
    const int row0 = bid * 16;
    const int rg = tid >> 5, cg = tid & 31;

    float4 acc[4];
#pragma unroll
    for (int r = 0; r < 4; r++) acc[r] = make_float4(0.f, 0.f, 0.f, 0.f);

    for (int kc = 0; kc < 49; kc++) {
        const int k0 = kc * 16;
        __syncthreads();
        {   // ws[kk][n] = win[n][k0+kk]; 256 threads, 8 values each
            const int n = tid & 127, h = tid >> 7;
            const float* wr = win + n * 784 + k0 + h * 8;
            float4 a = ld4(wr), b = ld4(wr + 4);
            ws[(h*8+0)*132 + n] = a.x; ws[(h*8+1)*132 + n] = a.y;
            ws[(h*8+2)*132 + n] = a.z; ws[(h*8+3)*132 + n] = a.w;
            ws[(h*8+4)*132 + n] = b.x; ws[(h*8+5)*132 + n] = b.y;
            ws[(h*8+6)*132 + n] = b.z; ws[(h*8+7)*132 + n] = b.w;
        }
        {
            const int r = tid >> 4, kk = tid & 15;
            xs[kk * 20 + r] = x[(row0 + r) * 784 + k0 + kk];
        }
        __syncthreads();
        if (tid < 128) {
#pragma unroll
            for (int kk = 0; kk < 16; kk++) {
                float4 wv = ld4(&ws[kk * 132 + cg * 4]);
#pragma unroll
                for (int rr = 0; rr < 4; rr++) {
                    float xv = xs[kk * 20 + rg * 4 + rr];
                    acc[rr].x += xv * wv.x; acc[rr].y += xv * wv.y;
                    acc[rr].z += xv * wv.z; acc[rr].w += xv * wv.w;
                }
            }
        }
    }

    if (tid < 128) {
        const float4 b4 = ld4(bin + cg * 4);
#pragma unroll
        for (int rr = 0; rr < 4; rr++) {
            const int row = row0 + rg * 4 + rr;
            float4 v;
            v.x = acc[rr].x + b4.x; v.y = acc[rr].y + b4.y;
            v.z = acc[rr].z + b4.z; v.w = acc[rr].w + b4.w;
            st4(&g_zin[row * 256 + cg * 4], v);
            float4 t;
            t.x = tanhf(v.x); t.y = tanhf(v.y); t.z = tanhf(v.z); t.w = tanhf(v.w);
            st4(&g_zin[row * 256 + 128 + cg * 4], t);
        }
    }
}

__global__ __launch_bounds__(256) void k_pre(const float* __restrict__ x,
                                             const float* __restrict__ win,
                                             const float* __restrict__ bin,
                                             const float* __restrict__ wblocks)
{
    extern __shared__ float sm[];
    if (blockIdx.x < 8) prep_body(sm, wblocks, blockIdx.x);
    else                input_body(sm, x, win, bin, blockIdx.x - 8);
}

// ---------------------------------------------------------------------------
// k_sweep smem layout (floats):
//   zin 0..4095 | zls 4096..36863 | qs 36864..38911 | wb 38912..55295 (2x8192)
//   bb 55296..56319 | lg 56320..56479 | mbar @56480 (2 x u64)
// ---------------------------------------------------------------------------
#define SW_FLOATS 56484
#define SW_BYTES  (SW_FLOATS * 4)

__device__ __forceinline__ void prefetch_chunk(int c, uint32_t wbB, uint32_t mbar0,
                                               const float* __restrict__ wblocks)
{
    if (c >= NCHUNKS) return;
    const uint32_t dst = wbB + (uint32_t)(c & 1) * 32768u;
    const uint32_t mb  = mbar0 + (uint32_t)(c & 1) * 8u;
    mbar_expect(mb, 32768u);
    if (c >= NCHUNKS - 2) {
        bulk_g2s(dst, g_WT + (c - (NCHUNKS - 2)) * 8192, 32768u, mb);
    } else {
        const int step = c / 6;
        const int l = step & 7;
        const int r = c - step * 6;
        if (r < 4) {
            bulk_g2s(dst,          g_Mt + l * 16384 + r * 4096, 16384u, mb);
            bulk_g2s(dst + 16384u, g_Nt + l * 16384 + r * 4096, 16384u, mb);
        } else {
            bulk_g2s(dst, wblocks + l * 16384 + (r - 4) * 8192, 32768u, mb);
        }
    }
}

__global__ __launch_bounds__(256, 1) void k_sweep(const float* __restrict__ wblocks,
                                                  const float* __restrict__ bblocks,
                                                  const float* __restrict__ wout,
                                                  const float* __restrict__ bout,
                                                  float* __restrict__ out)
{
    extern __shared__ float sm[];
    float* zin = sm;
    float* zls = sm + 4096;
    float* qs  = sm + 36864;
    float* wb  = sm + 38912;
    float* bb  = sm + 55296;
    float* lg  = sm + 56320;

    const uint32_t smem0 = s2u(sm);
    const uint32_t mbar0 = smem0 + 56480u * 4u;
    const uint32_t wbB   = smem0 + 38912u * 4u;

    const int tid  = threadIdx.x;
    const int wid  = tid >> 5;
    const int lane = tid & 31;
    const int rgrp = wid >> 2;        // 0..1 (8-row group)
    const int cq   = wid & 3;         // 0..3 (32-col quarter)
    const int r0   = rgrp * 8;
    const int col  = cq * 32 + lane;  // this lane's column (0..127)
    const int row0 = blockIdx.x * 16;

    for (int idx = tid; idx < 4096; idx += 256) zin[idx] = g_zin[row0 * 256 + idx];
    for (int idx = tid; idx < 1024; idx += 256) bb[idx] = bblocks[idx];
    if (tid == 0) {
        mbar_init(mbar0, 1);
        mbar_init(mbar0 + 8, 1);
        asm volatile("fence.mbarrier_init.release.cluster;" ::: "memory");
    }
    __syncthreads();
    for (int idx = tid; idx < 32768; idx += 256) zls[idx] = zin[idx & 4095];
    if (tid == 0) { prefetch_chunk(0, wbB, mbar0, wblocks); prefetch_chunk(1, wbB, mbar0, wblocks); }
    // initial q for step (0,0): q = 10*tanh(zin_u) + zin_v  (warp-owned region)
#pragma unroll
    for (int rr = 0; rr < 8; rr++) {
        const int r = r0 + rr;
        qs[r * 128 + col] = TANHK * tanhf(zin[r * 256 + col]) + zin[r * 256 + 128 + col];
    }
    __syncthreads();

    int c = 0;
    for (int it = 0; it < NSTEPS; it++) {
        for (int l = 0; l < NLAYERS; l++) {
            const float* carry = l ? (zls + (l - 1) * 4096) : zin;
            float* zl = zls + l * 4096;

            // ---- u = M p - N q ----
            float acc[8];
#pragma unroll
            for (int r = 0; r < 8; r++) acc[r] = 0.f;
            for (int kc = 0; kc < 4; kc++) {
                mbar_wait(mbar0 + (uint32_t)(c & 1) * 8u, (c >> 1) & 1);
                const float* Mt = wb + (c & 1) * 8192;
                const float* Nt = Mt + 4096;
#pragma unroll
                for (int kk4 = 0; kk4 < 8; kk4++) {
                    const int k0 = kc * 32 + kk4 * 4;
                    const int kb = kk4 * 4;
                    // weights for 4 k's, held in regs across all 8 rows
                    float mw[4], nw[4];
#pragma unroll
                    for (int t = 0; t < 4; t++) {
                        mw[t] = Mt[(kb + t) * 128 + col];
                        nw[t] = Nt[(kb + t) * 128 + col];
                    }
                    const float4 b4 = ld4(&bb[l * 128 + k0]);
#pragma unroll
                    for (int rr = 0; rr < 8; rr++) {
                        const int r = r0 + rr;
                        const float4 cu = ld4(&carry[r * 256 + k0]);
                        const float4 qq = ld4(&qs[r * 128 + k0]);
                        float a = acc[rr];
#pragma unroll
                        for (int t = 0; t < 4; t++) {
                            const float pv = fmaf(DT_A, FC(b4, t), FC(cu, t));
                            a = fmaf(pv, mw[t], a);
                            a = fmaf(-FC(qq, t), nw[t], a);
                        }
                        acc[rr] = a;
                    }
                }
                if (kc == 3) {   // store u before the slot-reuse barrier
#pragma unroll
                    for (int rr = 0; rr < 8; rr++)
                        zl[(r0 + rr) * 256 + col] = acc[rr];
                }
                __syncthreads();
                if (tid == 0) prefetch_chunk(c + 2, wbB, mbar0, wblocks);
                c++;
            }

            // ---- v = (q + a * u W)/c  (+fused next-step q) ----
            float vac[8];
#pragma unroll
            for (int r = 0; r < 8; r++) vac[r] = 0.f;
            for (int jc = 0; jc < 2; jc++) {
                mbar_wait(mbar0 + (uint32_t)(c & 1) * 8u, (c >> 1) & 1);
                const float* Ws = wb + (c & 1) * 8192;
#pragma unroll
                for (int jj4 = 0; jj4 < 16; jj4++) {
                    const int j0 = jc * 64 + jj4 * 4;
                    const int jb = jj4 * 4;
                    float w[4];
#pragma unroll
                    for (int t = 0; t < 4; t++) w[t] = Ws[(jb + t) * 128 + col];
#pragma unroll
                    for (int rr = 0; rr < 8; rr++) {
                        const float4 u4 = ld4(&zl[(r0 + rr) * 256 + j0]);
                        float a = vac[rr];
#pragma unroll
                        for (int t = 0; t < 4; t++) a = fmaf(FC(u4, t), w[t], a);
                        vac[rr] = a;
                    }
                }
                if (jc == 1) {   // epilogue: store v + stage next q, before barrier
                    const bool last = (l == NLAYERS - 1) && (it == NSTEPS - 1);
#pragma unroll
                    for (int rr = 0; rr < 8; rr++) {
                        const int r = r0 + rr;
                        const float q = qs[r * 128 + col];
                        const float v = (q + DT_A * vac[rr]) * INVC;
                        zl[r * 256 + 128 + col] = v;
                        if (!last) {
                            // next step: (it,l+1) or (it+1,0)
                            const float nu = (l < NLAYERS - 1)
                                ? zls[(l + 1) * 4096 + r * 256 + col]
                                : zls[r * 256 + col];
                            const float cv = (l < NLAYERS - 1)
                                ? v
                                : zin[r * 256 + 128 + col];
                            qs[r * 128 + col] = TANHK * tanhf(nu) + cv;
                        }
                    }
                }
                __syncthreads();
                if (tid == 0) prefetch_chunk(c + 2, wbB, mbar0, wblocks);
                c++;
            }
        }
    }

    // ---- final block: u_out = z_in_u + a*b7 - a*(v7 @ W7^T) -> qs ----
    {
        float uac[8];
#pragma unroll
        for (int r = 0; r < 8; r++) uac[r] = 0.f;
        const float* zl7 = zls + 7 * 4096;
        for (int ic = 0; ic < 2; ic++) {
            mbar_wait(mbar0 + (uint32_t)(c & 1) * 8u, (c >> 1) & 1);
            const float* Ws = wb + (c & 1) * 8192;   // WT rows ic*64..
#pragma unroll
            for (int ii4 = 0; ii4 < 16; ii4++) {
                const int i0 = ic * 64 + ii4 * 4;
                const int ib = ii4 * 4;
                float w[4];
#pragma unroll
                for (int t = 0; t < 4; t++) w[t] = Ws[(ib + t) * 128 + col];
#pragma unroll
                for (int rr = 0; rr < 8; rr++) {
                    const float4 v4 = ld4(&zl7[(r0 + rr) * 256 + 128 + i0]);
                    float a = uac[rr];
#pragma unroll
                    for (int t = 0; t < 4; t++) a = fmaf(FC(v4, t), w[t], a);
                    uac[rr] = a;
                }
            }
            if (ic == 1) {
#pragma unroll
                for (int rr = 0; rr < 8; rr++) {
                    const int r = r0 + rr;
                    qs[r * 128 + col] = zin[r * 256 + col]
                                      + DT_A * bb[7 * 128 + col]
                                      - DT_A * uac[rr];
                }
            }
            __syncthreads();
            c++;
        }
    }

    // ---- logits + softmax ----
    for (int t = tid; t < 160; t += 256) {
        const int r = t / 10, o = t % 10;
        const float* ur = qs + r * 128;
        const float* wr = wout + o * 128;
        float a = bout[o];
#pragma unroll 4
        for (int k = 0; k < U; k++) a += ur[k] * wr[k];
        lg[t] = a;
    }
    __syncthreads();
    if (tid < 16) {
        float mx = -1e30f;
#pragma unroll
        for (int o = 0; o < 10; o++) mx = fmaxf(mx, lg[tid * 10 + o]);
        float e[10], s = 0.f;
#pragma unroll
        for (int o = 0; o < 10; o++) { e[o] = expf(lg[tid * 10 + o] - mx); s += e[o]; }
        const float inv = 1.0f / s;
#pragma unroll
        for (int o = 0; o < 10; o++) out[(row0 + tid) * 10 + o] = e[o] * inv;
    }
}

// ---------------------------------------------------------------------------
extern "C" void kernel_launch(void* const* d_in, const int* in_sizes, int n_in,
                              void* d_out, int out_size)
{
    const float* x     = (const float*)d_in[0];
    const float* w_in  = (const float*)d_in[1];
    const float* b_in  = (const float*)d_in[2];
    const float* w_blk = (const float*)d_in[3];
    const float* b_blk = (const float*)d_in[4];
    const float* w_out = (const float*)d_in[5];
    const float* b_out = (const float*)d_in[6];
    float* out = (float*)d_out;

    cudaFuncSetAttribute(k_pre,   cudaFuncAttributeMaxDynamicSharedMemorySize, PREP_SMEM);
    cudaFuncSetAttribute(k_sweep, cudaFuncAttributeMaxDynamicSharedMemorySize, SW_BYTES);

    k_pre  <<<136, 256, PREP_SMEM>>>(x, w_in, b_in, w_blk);
    k_sweep<<<128, 256, SW_BYTES>>>(w_blk, b_blk, w_out, b_out, out);
}

// round 6
// speedup vs baseline: 1.0660x; 1.0660x over previous
#include <cuda_runtime.h>
#include <cstdint>
#include <math.h>

// ---------------------------------------------------------------------------
// TransNetSweeping on GB300 — fp32x2 (FFMA2) fused sweep (R5).
//
// Math: A_l = [[I, aW],[-aW^T, cI]], a=0.1, c=11.
//   S = I + (a^2/c) W W^T,  M = S^{-1},  Ntneg = -(a/c) M W (pre-negated)
//   u = M*carry_u + Mb + Ntneg q ;  Mb = 0.1*M b   (precomputed per layer)
//   v = (q + a W^T u)/c ;  q = 10*tanh(z_l_u) + carry_v
// Fixed 15 Gauss-Seidel sweeps.
//
// All activation state stored TRANSPOSED: xT[col][16 rows]. Lane owns one
// output column and 8 rows = 4 row-pairs held as f32x2; inner product uses
// fma.rn.f32x2 (2 FMA/instr). Weights scalar per lane, splat via mov.b64.
// Weights stream via cp.async.bulk double buffer (2x32KB), 722 chunks.
// ---------------------------------------------------------------------------

#define BATCH    2048
#define U        128
#define NLAYERS  8
#define NSTEPS   15

#define DT_A     0.1f
#define INVC     (1.0f/11.0f)
#define TANHK    10.0f

#define NCHUNKS  (NSTEPS * NLAYERS * 6 + 2)   // 722

typedef unsigned long long ull;

__device__ float g_zin[BATCH * 256];          // per 16-row blk: uT[2048]|vT[2048]
__device__ float g_Mt [NLAYERS * U * U];      // Mt[l][k][j] = M[j][k]
__device__ float g_Nt [NLAYERS * U * U];      // NEGATED: -(a/c) (M W), [k][j]
__device__ float g_Mb [NLAYERS * U];          // Mb[l][j] = 0.1 * sum_k M[j][k] b[k]
__device__ float g_WT [U * U];                // WT[i][k] = W7[k][i]

__device__ __forceinline__ float4 ld4(const float* p) { return *(const float4*)p; }
__device__ __forceinline__ void   st4(float* p, float4 v) { *(float4*)p = v; }
#define FC(v,t) (((const float*)&(v))[t])

__device__ __forceinline__ ull pk2(float x, float y) {
    ull r; asm("mov.b64 %0, {%1,%2};" : "=l"(r) : "f"(x), "f"(y)); return r;
}
__device__ __forceinline__ ull splat(float x) { return pk2(x, x); }
__device__ __forceinline__ ull fma2(ull a, ull b, ull c) {
    ull d; asm("fma.rn.f32x2 %0, %1, %2, %3;" : "=l"(d) : "l"(a), "l"(b), "l"(c)); return d;
}
__device__ __forceinline__ ull add2(ull a, ull b) {
    ull d; asm("add.rn.f32x2 %0, %1, %2;" : "=l"(d) : "l"(a), "l"(b)); return d;
}
__device__ __forceinline__ ull mul2(ull a, ull b) {
    ull d; asm("mul.rn.f32x2 %0, %1, %2;" : "=l"(d) : "l"(a), "l"(b)); return d;
}
__device__ __forceinline__ void unpk2(ull v, float& lo, float& hi) {
    asm("mov.b64 {%0,%1}, %2;" : "=f"(lo), "=f"(hi) : "l"(v));
}

__device__ __forceinline__ uint32_t s2u(const void* p) {
    uint32_t a;
    asm("{ .reg .u64 t; cvta.to.shared.u64 t, %1; cvt.u32.u64 %0, t; }" : "=r"(a) : "l"(p));
    return a;
}
__device__ __forceinline__ void mbar_init(uint32_t m, uint32_t cnt) {
    asm volatile("mbarrier.init.shared.b64 [%0], %1;" :: "r"(m), "r"(cnt) : "memory");
}
__device__ __forceinline__ void mbar_expect(uint32_t m, uint32_t tx) {
    asm volatile("mbarrier.arrive.expect_tx.shared.b64 _, [%0], %1;" :: "r"(m), "r"(tx) : "memory");
}
__device__ __forceinline__ void bulk_g2s(uint32_t dst, const void* src, uint32_t bytes, uint32_t m) {
    asm volatile("cp.async.bulk.shared::cluster.global.mbarrier::complete_tx::bytes [%0], [%1], %2, [%3];"
                 :: "r"(dst), "l"(src), "r"(bytes), "r"(m) : "memory");
}
__device__ __forceinline__ void mbar_wait(uint32_t m, uint32_t phase) {
    uint32_t done;
    do {
        asm volatile("{\n\t.reg .pred p;\n\t"
                     "mbarrier.try_wait.parity.acquire.cta.shared::cta.b64 p, [%1], %2, 0x989680;\n\t"
                     "selp.b32 %0, 1, 0, p;\n\t}"
                     : "=r"(done) : "r"(m), "r"(phase) : "memory");
    } while (!done);
}

// ---------------------------------------------------------------------------
// k_pre: merged prep (CTAs 0..7) + input projection (CTAs 8..135). Block 256.
// ---------------------------------------------------------------------------
#define WS_S 129
#define AS_S 260
#define PREP_SMEM ((128*WS_S + 128*AS_S + 128) * 4)

__device__ void prep_body(float* sm, const float* __restrict__ wblocks,
                          const float* __restrict__ bblocks, int l)
{
    float* Wsh  = sm;
    float* aug  = sm + 128 * WS_S;
    float* colb = aug + 128 * AS_S;
    const int tid = threadIdx.x;
    const float* Wg = wblocks + l * U * U;

    for (int idx = tid; idx < U * U; idx += 256)
        Wsh[(idx >> 7) * WS_S + (idx & 127)] = Wg[idx];
    __syncthreads();

    const float kscl = (DT_A * DT_A) * INVC;
#pragma unroll 1
    for (int rep = 0; rep < 2; rep++) {
        const int pos = tid + rep * 256;
        const int ti = pos >> 4, tj = pos & 15;
        float acc[4][8];
#pragma unroll
        for (int r = 0; r < 4; r++)
#pragma unroll
            for (int j = 0; j < 8; j++) acc[r][j] = 0.f;
        for (int k = 0; k < U; k++) {
            float wi[4], wj[8];
#pragma unroll
            for (int r = 0; r < 4; r++) wi[r] = Wsh[(ti*4 + r) * WS_S + k];
#pragma unroll
            for (int j = 0; j < 8; j++) wj[j] = Wsh[(tj*8 + j) * WS_S + k];
#pragma unroll
            for (int r = 0; r < 4; r++)
#pragma unroll
                for (int j = 0; j < 8; j++) acc[r][j] += wi[r] * wj[j];
        }
#pragma unroll
        for (int r = 0; r < 4; r++)
#pragma unroll
            for (int j = 0; j < 8; j++) {
                int i = ti*4 + r, jj = tj*8 + j;
                aug[i * AS_S + jj] = kscl * acc[r][j] + (i == jj ? 1.f : 0.f);
            }
    }
    for (int idx = tid; idx < U * U; idx += 256) {
        int i = idx >> 7, j = idx & 127;
        aug[i * AS_S + 128 + j] = (i == j) ? 1.f : 0.f;
    }

    const int f4c = tid & 63, rgp = tid >> 6;
    for (int p = 0; p < U; p++) {
        __syncthreads();
        const float inv = 1.0f / aug[p * AS_S + p];
        if (tid < 128 && tid != p) colb[tid] = aug[tid * AS_S + p];
        __syncthreads();
        aug[p * AS_S + tid] *= inv;
        __syncthreads();
        const float4 rp = ld4(&aug[p * AS_S + f4c * 4]);
        for (int i = rgp * 32; i < rgp * 32 + 32; i++) {
            if (i == p) continue;
            const float fac = colb[i];
            float4 a = ld4(&aug[i * AS_S + f4c * 4]);
            a.x -= fac * rp.x; a.y -= fac * rp.y;
            a.z -= fac * rp.z; a.w -= fac * rp.w;
            st4(&aug[i * AS_S + f4c * 4], a);
        }
    }
    __syncthreads();

    // aug_left[m][j] := M[j][m]
    for (int idx = tid; idx < U * U; idx += 256) {
        int m = idx >> 7, j = idx & 127;
        aug[m * AS_S + j] = aug[j * AS_S + 128 + m];
    }
    __syncthreads();

    // Mt[l][k][j] = M[j][k]
    for (int idx = tid; idx < U * U; idx += 256) {
        int k = idx >> 7, j = idx & 127;
        g_Mt[l * U * U + idx] = aug[k * AS_S + j];
    }

    // Mb[l][j] = 0.1 * sum_m M[j][m] b[m] = 0.1 * sum_m aug_left[m][j] b[m]
    if (tid < 128) {
        float s = 0.f;
        for (int m = 0; m < U; m++)
            s += aug[m * AS_S + tid] * bblocks[l * U + m];
        g_Mb[l * U + tid] = DT_A * s;
    }

    // Nt (NEGATED): g_Nt[l][k][j] = -(a/c) sum_m aug_left[m][j] * Wsh[m][k]
    const float ac = -DT_A * INVC;
#pragma unroll 1
    for (int rep = 0; rep < 2; rep++) {
        const int pos = tid + rep * 256;
        const int tk = pos >> 4, tj = pos & 15;
        float acc[4][8];
#pragma unroll
        for (int r = 0; r < 4; r++)
#pragma unroll
            for (int j = 0; j < 8; j++) acc[r][j] = 0.f;
        for (int m = 0; m < U; m++) {
            float wv[4], mv[8];
#pragma unroll
            for (int r = 0; r < 4; r++) wv[r] = Wsh[m * WS_S + tk*4 + r];
#pragma unroll
            for (int j = 0; j < 8; j++) mv[j] = aug[m * AS_S + tj*8 + j];
#pragma unroll
            for (int r = 0; r < 4; r++)
#pragma unroll
                for (int j = 0; j < 8; j++) acc[r][j] += wv[r] * mv[j];
        }
#pragma unroll
        for (int r = 0; r < 4; r++)
#pragma unroll
            for (int j = 0; j < 8; j++)
                g_Nt[l * U * U + (tk*4 + r) * U + tj*8 + j] = ac * acc[r][j];
    }

    if (l == NLAYERS - 1) {
        for (int idx = tid; idx < U * U; idx += 256) {
            int i = idx >> 7, j = idx & 127;
            g_WT[i * U + j] = Wsh[j * WS_S + i];
        }
    }
}

__device__ void input_body(float* sm, const float* __restrict__ x,
                           const float* __restrict__ win,
                           const float* __restrict__ bin, int bid)
{
    float* ws = sm;            // [16][132]
    float* xs = sm + 16 * 132; // [16][20]
    const int tid = threadIdx.x;
    const int row0 = bid * 16;
    const int rg = tid >> 5, cg = tid & 31;

    float4 acc[4];
#pragma unroll
    for (int r = 0; r < 4; r++) acc[r] = make_float4(0.f, 0.f, 0.f, 0.f);

    for (int kc = 0; kc < 49; kc++) {
        const int k0 = kc * 16;
        __syncthreads();
        {
            const int n = tid & 127, h = tid >> 7;
            const float* wr = win + n * 784 + k0 + h * 8;
            float4 a = ld4(wr), b = ld4(wr + 4);
            ws[(h*8+0)*132 + n] = a.x; ws[(h*8+1)*132 + n] = a.y;
            ws[(h*8+2)*132 + n] = a.z; ws[(h*8+3)*132 + n] = a.w;
            ws[(h*8+4)*132 + n] = b.x; ws[(h*8+5)*132 + n] = b.y;
            ws[(h*8+6)*132 + n] = b.z; ws[(h*8+7)*132 + n] = b.w;
        }
        {
            const int r = tid >> 4, kk = tid & 15;
            xs[kk * 20 + r] = x[(row0 + r) * 784 + k0 + kk];
        }
        __syncthreads();
        if (tid < 128) {
#pragma unroll
            for (int kk = 0; kk < 16; kk++) {
                float4 wv = ld4(&ws[kk * 132 + cg * 4]);
#pragma unroll
                for (int rr = 0; rr < 4; rr++) {
                    float xv = xs[kk * 20 + rg * 4 + rr];
                    acc[rr].x += xv * wv.x; acc[rr].y += xv * wv.y;
                    acc[rr].z += xv * wv.z; acc[rr].w += xv * wv.w;
                }
            }
        }
    }

    if (tid < 128) {
        const float4 b4 = ld4(bin + cg * 4);
#pragma unroll
        for (int rr = 0; rr < 4; rr++) {
            acc[rr].x += b4.x; acc[rr].y += b4.y;
            acc[rr].z += b4.z; acc[rr].w += b4.w;
        }
        // transposed store: g_zin[blk][ uT: c*16+r | vT: 2048 + c*16+r ]
        float* base = g_zin + bid * 4096;
#pragma unroll
        for (int cc = 0; cc < 4; cc++) {
            const int col = cg * 4 + cc;
#pragma unroll
            for (int rp = 0; rp < 2; rp++) {
                const float a0 = FC(acc[rp*2],   cc);
                const float a1 = FC(acc[rp*2+1], cc);
                *(ull*)&base[col * 16 + rg * 4 + rp * 2]        = pk2(a0, a1);
                *(ull*)&base[2048 + col * 16 + rg * 4 + rp * 2] = pk2(tanhf(a0), tanhf(a1));
            }
        }
    }
}

__global__ __launch_bounds__(256) void k_pre(const float* __restrict__ x,
                                             const float* __restrict__ win,
                                             const float* __restrict__ bin,
                                             const float* __restrict__ wblocks,
                                             const float* __restrict__ bblocks)
{
    extern __shared__ float sm[];
    if (blockIdx.x < 8) prep_body(sm, wblocks, bblocks, blockIdx.x);
    else                input_body(sm, x, win, bin, blockIdx.x - 8);
}

// ---------------------------------------------------------------------------
// k_sweep smem layout (floats):
//   zinT 0..4095 | zls 4096..36863 (8 x [uT 2048|vT 2048]) | qT 36864..38911
//   wb 38912..55295 (2x8192) | bb 55296..56319 | Mbs 56320..57343
//   lg 57344..57503 | mbar @57504 (2 x u64)
// ---------------------------------------------------------------------------
#define SW_FLOATS 57508
#define SW_BYTES  (SW_FLOATS * 4)

__device__ __forceinline__ void prefetch_chunk(int c, uint32_t wbB, uint32_t mbar0,
                                               const float* __restrict__ wblocks)
{
    if (c >= NCHUNKS) return;
    const uint32_t dst = wbB + (uint32_t)(c & 1) * 32768u;
    const uint32_t mb  = mbar0 + (uint32_t)(c & 1) * 8u;
    mbar_expect(mb, 32768u);
    if (c >= NCHUNKS - 2) {
        bulk_g2s(dst, g_WT + (c - (NCHUNKS - 2)) * 8192, 32768u, mb);
    } else {
        const int step = c / 6;
        const int l = step & 7;
        const int r = c - step * 6;
        if (r < 4) {
            bulk_g2s(dst,          g_Mt + l * 16384 + r * 4096, 16384u, mb);
            bulk_g2s(dst + 16384u, g_Nt + l * 16384 + r * 4096, 16384u, mb);
        } else {
            bulk_g2s(dst, wblocks + l * 16384 + (r - 4) * 8192, 32768u, mb);
        }
    }
}

__global__ __launch_bounds__(256, 1) void k_sweep(const float* __restrict__ wblocks,
                                                  const float* __restrict__ bblocks,
                                                  const float* __restrict__ wout,
                                                  const float* __restrict__ bout,
                                                  float* __restrict__ out)
{
    extern __shared__ float sm[];
    float* zinT = sm;
    float* zls  = sm + 4096;
    float* qT   = sm + 36864;
    float* wb   = sm + 38912;
    float* bb   = sm + 55296;
    float* Mbs  = sm + 56320;
    float* lg   = sm + 57344;

    const uint32_t smem0 = s2u(sm);
    const uint32_t mbar0 = smem0 + 57504u * 4u;
    const uint32_t wbB   = smem0 + 38912u * 4u;

    const int tid  = threadIdx.x;
    const int wid  = tid >> 5;
    const int lane = tid & 31;
    const int h8   = (wid >> 2) * 8;       // row half offset (0 or 8)
    const int col  = (wid & 3) * 32 + lane; // lane's column 0..127
    const int row0 = blockIdx.x * 16;

    // staging map (all 256 threads): 4 k's x 1 row-pair each
    const int rp2 = (tid & 7) * 2;
    const int kg4 = (tid >> 3) * 4;

    for (int idx = tid; idx < 4096; idx += 256) zinT[idx] = g_zin[row0 * 256 + idx];
    for (int idx = tid; idx < 1024; idx += 256) bb[idx] = bblocks[idx];
    for (int idx = tid; idx < 1024; idx += 256) Mbs[idx] = g_Mb[idx];
    if (tid == 0) {
        mbar_init(mbar0, 1);
        mbar_init(mbar0 + 8, 1);
        asm volatile("fence.mbarrier_init.release.cluster;" ::: "memory");
    }
    __syncthreads();
    for (int idx = tid; idx < 32768; idx += 256) zls[idx] = zinT[idx & 4095];
    if (tid == 0) { prefetch_chunk(0, wbB, mbar0, wblocks); prefetch_chunk(1, wbB, mbar0, wblocks); }
    __syncthreads();

    int c = 0;
    for (int it = 0; it < NSTEPS; it++) {
        for (int l = 0; l < NLAYERS; l++) {
            const float* cuT = l ? (zls + (l - 1) * 4096) : zinT;          // carry uT
            const float* cvT = l ? (zls + (l - 1) * 4096 + 2048) : (zinT + 2048);
            float* uTl = zls + l * 4096;
            float* vTl = uTl + 2048;

            // ---- stage qT[k][r] = 10*tanh(uTl[k][r]) + cvT[k][r] ----
#pragma unroll
            for (int ki = 0; ki < 4; ki++) {
                const int base = (kg4 + ki) * 16 + rp2;
                const float2 u2 = *(const float2*)&uTl[base];
                const float2 v2 = *(const float2*)&cvT[base];
                float2 q2;
                q2.x = TANHK * tanhf(u2.x) + v2.x;
                q2.y = TANHK * tanhf(u2.y) + v2.y;
                *(float2*)&qT[base] = q2;
            }
            __syncthreads();

            // ---- u = M*carry + Mb + Ntneg*q ----
            ull acc0, acc1, acc2, acc3;
            {
                const ull mb2 = splat(Mbs[l * 128 + col]);
                acc0 = mb2; acc1 = mb2; acc2 = mb2; acc3 = mb2;
            }
            for (int kc = 0; kc < 4; kc++) {
                mbar_wait(mbar0 + (uint32_t)(c & 1) * 8u, (c >> 1) & 1);
                const float* Mt = wb + (c & 1) * 8192;
                const float* Nt = Mt + 4096;
#pragma unroll
                for (int kk4 = 0; kk4 < 8; kk4++) {
                    const int kb = kk4 * 4;
                    const int k0 = kc * 32 + kb;
                    ull mw[4], nw[4];
#pragma unroll
                    for (int t = 0; t < 4; t++) {
                        mw[t] = splat(Mt[(kb + t) * 128 + col]);
                        nw[t] = splat(Nt[(kb + t) * 128 + col]);
                    }
#pragma unroll
                    for (int t = 0; t < 4; t++) {
                        const ulonglong2 cuA = *(const ulonglong2*)&cuT[(k0 + t) * 16 + h8];
                        const ulonglong2 cuB = *(const ulonglong2*)&cuT[(k0 + t) * 16 + h8 + 4];
                        const ulonglong2 qA  = *(const ulonglong2*)&qT [(k0 + t) * 16 + h8];
                        const ulonglong2 qB  = *(const ulonglong2*)&qT [(k0 + t) * 16 + h8 + 4];
                        acc0 = fma2(mw[t], cuA.x, acc0);
                        acc1 = fma2(mw[t], cuA.y, acc1);
                        acc2 = fma2(mw[t], cuB.x, acc2);
                        acc3 = fma2(mw[t], cuB.y, acc3);
                        acc0 = fma2(nw[t], qA.x, acc0);
                        acc1 = fma2(nw[t], qA.y, acc1);
                        acc2 = fma2(nw[t], qB.x, acc2);
                        acc3 = fma2(nw[t], qB.y, acc3);
                    }
                }
                if (kc == 3) {   // store uT before the slot-reuse barrier
                    *(ull*)&uTl[col * 16 + h8    ] = acc0;
                    *(ull*)&uTl[col * 16 + h8 + 2] = acc1;
                    *(ull*)&uTl[col * 16 + h8 + 4] = acc2;
                    *(ull*)&uTl[col * 16 + h8 + 6] = acc3;
                }
                __syncthreads();
                if (tid == 0) prefetch_chunk(c + 2, wbB, mbar0, wblocks);
                c++;
            }

            // ---- v = (q + 0.1 * u W)/11 ----
            ull vac0 = 0, vac1 = 0, vac2 = 0, vac3 = 0;
            for (int jc = 0; jc < 2; jc++) {
                mbar_wait(mbar0 + (uint32_t)(c & 1) * 8u, (c >> 1) & 1);
                const float* Ws = wb + (c & 1) * 8192;
#pragma unroll
                for (int jj4 = 0; jj4 < 16; jj4++) {
                    const int jb = jj4 * 4;
                    const int j0 = jc * 64 + jb;
                    ull w2[4];
#pragma unroll
                    for (int t = 0; t < 4; t++) w2[t] = splat(Ws[(jb + t) * 128 + col]);
#pragma unroll
                    for (int t = 0; t < 4; t++) {
                        const ulonglong2 uA = *(const ulonglong2*)&uTl[(j0 + t) * 16 + h8];
                        const ulonglong2 uB = *(const ulonglong2*)&uTl[(j0 + t) * 16 + h8 + 4];
                        vac0 = fma2(w2[t], uA.x, vac0);
                        vac1 = fma2(w2[t], uA.y, vac1);
                        vac2 = fma2(w2[t], uB.x, vac2);
                        vac3 = fma2(w2[t], uB.y, vac3);
                    }
                }
                if (jc == 1) {   // epilogue: v = (q + 0.1*S)/11, store vT
                    const ull a2 = splat(DT_A), ic2 = splat(INVC);
                    const int cb = col * 16 + h8;
                    const ull q0 = *(const ull*)&qT[cb    ];
                    const ull q1 = *(const ull*)&qT[cb + 2];
                    const ull q2 = *(const ull*)&qT[cb + 4];
                    const ull q3 = *(const ull*)&qT[cb + 6];
                    *(ull*)&vTl[cb    ] = mul2(fma2(vac0, a2, q0), ic2);
                    *(ull*)&vTl[cb + 2] = mul2(fma2(vac1, a2, q1), ic2);
                    *(ull*)&vTl[cb + 4] = mul2(fma2(vac2, a2, q2), ic2);
                    *(ull*)&vTl[cb + 6] = mul2(fma2(vac3, a2, q3), ic2);
                }
                __syncthreads();
                if (tid == 0) prefetch_chunk(c + 2, wbB, mbar0, wblocks);
                c++;
            }
        }
    }

    // ---- final block: u_out = zin_u + 0.1*b7 - 0.1*(v7 @ W7^T), row-major -> qT ----
    {
        ull ua0 = 0, ua1 = 0, ua2 = 0, ua3 = 0;
        const float* vT7 = zls + 7 * 4096 + 2048;
        for (int ic = 0; ic < 2; ic++) {
            mbar_wait(mbar0 + (uint32_t)(c & 1) * 8u, (c >> 1) & 1);
            const float* Ws = wb + (c & 1) * 8192;   // WT rows ic*64..
#pragma unroll
            for (int ii4 = 0; ii4 < 16; ii4++) {
                const int ib = ii4 * 4;
                const int i0 = ic * 64 + ib;
                ull w2[4];
#pragma unroll
                for (int t = 0; t < 4; t++) w2[t] = splat(Ws[(ib + t) * 128 + col]);
#pragma unroll
                for (int t = 0; t < 4; t++) {
                    const ulonglong2 vA = *(const ulonglong2*)&vT7[(i0 + t) * 16 + h8];
                    const ulonglong2 vB = *(const ulonglong2*)&vT7[(i0 + t) * 16 + h8 + 4];
                    ua0 = fma2(w2[t], vA.x, ua0);
                    ua1 = fma2(w2[t], vA.y, ua1);
                    ua2 = fma2(w2[t], vB.x, ua2);
                    ua3 = fma2(w2[t], vB.y, ua3);
                }
            }
            if (ic == 1) {
                const float bt = DT_A * bb[7 * 128 + col];
                const ull bt2 = splat(bt);
                const ull na2 = splat(-DT_A);
                const int cb = col * 16 + h8;
                ull r01 = fma2(ua0, na2, add2(*(const ull*)&zinT[cb    ], bt2));
                ull r23 = fma2(ua1, na2, add2(*(const ull*)&zinT[cb + 2], bt2));
                ull r45 = fma2(ua2, na2, add2(*(const ull*)&zinT[cb + 4], bt2));
                ull r67 = fma2(ua3, na2, add2(*(const ull*)&zinT[cb + 6], bt2));
                float a, b2;
                unpk2(r01, a, b2); qT[(h8+0)*128+col] = a; qT[(h8+1)*128+col] = b2;
                unpk2(r23, a, b2); qT[(h8+2)*128+col] = a; qT[(h8+3)*128+col] = b2;
                unpk2(r45, a, b2); qT[(h8+4)*128+col] = a; qT[(h8+5)*128+col] = b2;
                unpk2(r67, a, b2); qT[(h8+6)*128+col] = a; qT[(h8+7)*128+col] = b2;
            }
            __syncthreads();
            c++;
        }
    }

    // ---- logits + softmax (qT now holds u_out row-major [r][128]) ----
    for (int t = tid; t < 160; t += 256) {
        const int r = t / 10, o = t % 10;
        const float* ur = qT + r * 128;
        const float* wr = wout + o * 128;
        float a = bout[o];
#pragma unroll 4
        for (int k = 0; k < U; k++) a += ur[k] * wr[k];
        lg[t] = a;
    }
    __syncthreads();
    if (tid < 16) {
        float mx = -1e30f;
#pragma unroll
        for (int o = 0; o < 10; o++) mx = fmaxf(mx, lg[tid * 10 + o]);
        float e[10], s = 0.f;
#pragma unroll
        for (int o = 0; o < 10; o++) { e[o] = expf(lg[tid * 10 + o] - mx); s += e[o]; }
        const float inv = 1.0f / s;
#pragma unroll
        for (int o = 0; o < 10; o++) out[(row0 + tid) * 10 + o] = e[o] * inv;
    }
}

// ---------------------------------------------------------------------------
extern "C" void kernel_launch(void* const* d_in, const int* in_sizes, int n_in,
                              void* d_out, int out_size)
{
    const float* x     = (const float*)d_in[0];
    const float* w_in  = (const float*)d_in[1];
    const float* b_in  = (const float*)d_in[2];
    const float* w_blk = (const float*)d_in[3];
    const float* b_blk = (const float*)d_in[4];
    const float* w_out = (const float*)d_in[5];
    const float* b_out = (const float*)d_in[6];
    float* out = (float*)d_out;

    cudaFuncSetAttribute(k_pre,   cudaFuncAttributeMaxDynamicSharedMemorySize, PREP_SMEM);
    cudaFuncSetAttribute(k_sweep, cudaFuncAttributeMaxDynamicSharedMemorySize, SW_BYTES);

    k_pre  <<<136, 256, PREP_SMEM>>>(x, w_in, b_in, w_blk, b_blk);
    k_sweep<<<128, 256, SW_BYTES>>>(w_blk, b_blk, w_out, b_out, out);
}

// round 7
// speedup vs baseline: 1.0794x; 1.0126x over previous
#include <cuda_runtime.h>
#include <cstdint>
#include <math.h>

// ---------------------------------------------------------------------------
// TransNetSweeping on GB300 — f32x2, col-pair accumulators, 512-thread
// k-split sweep (R6).
//
// u = M*carry_u + Mb + Ntneg*q ;  v = (q + a W^T u)/c ; q = 10*tanh(u_l)+carry_v
// Fixed 15 Gauss-Seidel sweeps.
//
// k_sweep: 128 CTAs x 512 thr (16 warps = 2 k-split x 2 row-half x 4 col-q).
// Lane = 4 rows x 1 colpair; acc f32x2 over columns. Weight loads LDS.64
// (full 128B wavefronts); activation loads one LDS.128 per matrix per k.
// k-split partials combined through the destination smem buffers.
// ---------------------------------------------------------------------------

#define BATCH    2048
#define U        128
#define NLAYERS  8
#define NSTEPS   15

#define DT_A     0.1f
#define INVC     (1.0f/11.0f)
#define TANHK    10.0f

#define NCHUNKS  (NSTEPS * NLAYERS * 6 + 2)   // 722

typedef unsigned long long ull;

__device__ float g_zin[BATCH * 256];          // per 16-row blk: uT[2048]|vT[2048]
__device__ float g_Mt [NLAYERS * U * U];      // Mt[l][k][j] = M[j][k]
__device__ float g_Nt [NLAYERS * U * U];      // NEGATED: -(a/c) (M W), [k][j]
__device__ float g_Mb [NLAYERS * U];          // Mb[l][j] = 0.1 * sum_k M[j][k] b[k]
__device__ float g_WT [U * U];                // WT[i][k] = W7[k][i]

__device__ __forceinline__ float4 ld4(const float* p) { return *(const float4*)p; }
__device__ __forceinline__ void   st4(float* p, float4 v) { *(float4*)p = v; }
#define FC(v,t) (((const float*)&(v))[t])

__device__ __forceinline__ ull pk2(float x, float y) {
    ull r; asm("mov.b64 %0, {%1,%2};" : "=l"(r) : "f"(x), "f"(y)); return r;
}
__device__ __forceinline__ ull splat(float x) { return pk2(x, x); }
__device__ __forceinline__ ull fma2(ull a, ull b, ull c) {
    ull d; asm("fma.rn.f32x2 %0, %1, %2, %3;" : "=l"(d) : "l"(a), "l"(b), "l"(c)); return d;
}
__device__ __forceinline__ void unpk2(ull v, float& lo, float& hi) {
    asm("mov.b64 {%0,%1}, %2;" : "=f"(lo), "=f"(hi) : "l"(v));
}

__device__ __forceinline__ uint32_t s2u(const void* p) {
    uint32_t a;
    asm("{ .reg .u64 t; cvta.to.shared.u64 t, %1; cvt.u32.u64 %0, t; }" : "=r"(a) : "l"(p));
    return a;
}
__device__ __forceinline__ void mbar_init(uint32_t m, uint32_t cnt) {
    asm volatile("mbarrier.init.shared.b64 [%0], %1;" :: "r"(m), "r"(cnt) : "memory");
}
__device__ __forceinline__ void mbar_expect(uint32_t m, uint32_t tx) {
    asm volatile("mbarrier.arrive.expect_tx.shared.b64 _, [%0], %1;" :: "r"(m), "r"(tx) : "memory");
}
__device__ __forceinline__ void bulk_g2s(uint32_t dst, const void* src, uint32_t bytes, uint32_t m) {
    asm volatile("cp.async.bulk.shared::cluster.global.mbarrier::complete_tx::bytes [%0], [%1], %2, [%3];"
                 :: "r"(dst), "l"(src), "r"(bytes), "r"(m) : "memory");
}
__device__ __forceinline__ void mbar_wait(uint32_t m, uint32_t phase) {
    uint32_t done;
    do {
        asm volatile("{\n\t.reg .pred p;\n\t"
                     "mbarrier.try_wait.parity.acquire.cta.shared::cta.b64 p, [%1], %2, 0x989680;\n\t"
                     "selp.b32 %0, 1, 0, p;\n\t}"
                     : "=r"(done) : "r"(m), "r"(phase) : "memory");
    } while (!done);
}

// ---------------------------------------------------------------------------
// k_pre: merged prep (CTAs 0..7) + input projection (CTAs 8..135). Block 256.
// ---------------------------------------------------------------------------
#define WS_S 129
#define AS_S 260
#define PREP_SMEM ((128*WS_S + 128*AS_S + 128) * 4)

__device__ void prep_body(float* sm, const float* __restrict__ wblocks,
                          const float* __restrict__ bblocks, int l)
{
    float* Wsh  = sm;
    float* aug  = sm + 128 * WS_S;
    float* colb = aug + 128 * AS_S;
    const int tid = threadIdx.x;
    const float* Wg = wblocks + l * U * U;

    for (int idx = tid; idx < U * U; idx += 256)
        Wsh[(idx >> 7) * WS_S + (idx & 127)] = Wg[idx];
    __syncthreads();

    const float kscl = (DT_A * DT_A) * INVC;
#pragma unroll 1
    for (int rep = 0; rep < 2; rep++) {
        const int pos = tid + rep * 256;
        const int ti = pos >> 4, tj = pos & 15;
        float acc[4][8];
#pragma unroll
        for (int r = 0; r < 4; r++)
#pragma unroll
            for (int j = 0; j < 8; j++) acc[r][j] = 0.f;
        for (int k = 0; k < U; k++) {
            float wi[4], wj[8];
#pragma unroll
            for (int r = 0; r < 4; r++) wi[r] = Wsh[(ti*4 + r) * WS_S + k];
#pragma unroll
            for (int j = 0; j < 8; j++) wj[j] = Wsh[(tj*8 + j) * WS_S + k];
#pragma unroll
            for (int r = 0; r < 4; r++)
#pragma unroll
                for (int j = 0; j < 8; j++) acc[r][j] += wi[r] * wj[j];
        }
#pragma unroll
        for (int r = 0; r < 4; r++)
#pragma unroll
            for (int j = 0; j < 8; j++) {
                int i = ti*4 + r, jj = tj*8 + j;
                aug[i * AS_S + jj] = kscl * acc[r][j] + (i == jj ? 1.f : 0.f);
            }
    }
    for (int idx = tid; idx < U * U; idx += 256) {
        int i = idx >> 7, j = idx & 127;
        aug[i * AS_S + 128 + j] = (i == j) ? 1.f : 0.f;
    }

    const int f4c = tid & 63, rgp = tid >> 6;
    for (int p = 0; p < U; p++) {
        __syncthreads();
        const float inv = 1.0f / aug[p * AS_S + p];
        if (tid < 128 && tid != p) colb[tid] = aug[tid * AS_S + p];
        __syncthreads();
        aug[p * AS_S + tid] *= inv;
        __syncthreads();
        const float4 rp = ld4(&aug[p * AS_S + f4c * 4]);
        for (int i = rgp * 32; i < rgp * 32 + 32; i++) {
            if (i == p) continue;
            const float fac = colb[i];
            float4 a = ld4(&aug[i * AS_S + f4c * 4]);
            a.x -= fac * rp.x; a.y -= fac * rp.y;
            a.z -= fac * rp.z; a.w -= fac * rp.w;
            st4(&aug[i * AS_S + f4c * 4], a);
        }
    }
    __syncthreads();

    // aug_left[m][j] := M[j][m]
    for (int idx = tid; idx < U * U; idx += 256) {
        int m = idx >> 7, j = idx & 127;
        aug[m * AS_S + j] = aug[j * AS_S + 128 + m];
    }
    __syncthreads();

    // Mt[l][k][j] = M[j][k]
    for (int idx = tid; idx < U * U; idx += 256) {
        int k = idx >> 7, j = idx & 127;
        g_Mt[l * U * U + idx] = aug[k * AS_S + j];
    }

    // Mb[l][j] = 0.1 * sum_m M[j][m] b[m]
    if (tid < 128) {
        float s = 0.f;
        for (int m = 0; m < U; m++)
            s += aug[m * AS_S + tid] * bblocks[l * U + m];
        g_Mb[l * U + tid] = DT_A * s;
    }

    // Nt (NEGATED): g_Nt[l][k][j] = -(a/c) sum_m aug_left[m][j] * Wsh[m][k]
    const float ac = -DT_A * INVC;
#pragma unroll 1
    for (int rep = 0; rep < 2; rep++) {
        const int pos = tid + rep * 256;
        const int tk = pos >> 4, tj = pos & 15;
        float acc[4][8];
#pragma unroll
        for (int r = 0; r < 4; r++)
#pragma unroll
            for (int j = 0; j < 8; j++) acc[r][j] = 0.f;
        for (int m = 0; m < U; m++) {
            float wv[4], mv[8];
#pragma unroll
            for (int r = 0; r < 4; r++) wv[r] = Wsh[m * WS_S + tk*4 + r];
#pragma unroll
            for (int j = 0; j < 8; j++) mv[j] = aug[m * AS_S + tj*8 + j];
#pragma unroll
            for (int r = 0; r < 4; r++)
#pragma unroll
                for (int j = 0; j < 8; j++) acc[r][j] += wv[r] * mv[j];
        }
#pragma unroll
        for (int r = 0; r < 4; r++)
#pragma unroll
            for (int j = 0; j < 8; j++)
                g_Nt[l * U * U + (tk*4 + r) * U + tj*8 + j] = ac * acc[r][j];
    }

    if (l == NLAYERS - 1) {
        for (int idx = tid; idx < U * U; idx += 256) {
            int i = idx >> 7, j = idx & 127;
            g_WT[i * U + j] = Wsh[j * WS_S + i];
        }
    }
}

__device__ void input_body(float* sm, const float* __restrict__ x,
                           const float* __restrict__ win,
                           const float* __restrict__ bin, int bid)
{
    float* ws = sm;            // [16][132]
    float* xs = sm + 16 * 132; // [16][20]
    const int tid = threadIdx.x;
    const int row0 = bid * 16;
    const int rg = tid >> 5, cg = tid & 31;

    float4 acc[4];
#pragma unroll
    for (int r = 0; r < 4; r++) acc[r] = make_float4(0.f, 0.f, 0.f, 0.f);

    for (int kc = 0; kc < 49; kc++) {
        const int k0 = kc * 16;
        __syncthreads();
        {
            const int n = tid & 127, h = tid >> 7;
            const float* wr = win + n * 784 + k0 + h * 8;
            float4 a = ld4(wr), b = ld4(wr + 4);
            ws[(h*8+0)*132 + n] = a.x; ws[(h*8+1)*132 + n] = a.y;
            ws[(h*8+2)*132 + n] = a.z; ws[(h*8+3)*132 + n] = a.w;
            ws[(h*8+4)*132 + n] = b.x; ws[(h*8+5)*132 + n] = b.y;
            ws[(h*8+6)*132 + n] = b.z; ws[(h*8+7)*132 + n] = b.w;
        }
        {
            const int r = tid >> 4, kk = tid & 15;
            xs[kk * 20 + r] = x[(row0 + r) * 784 + k0 + kk];
        }
        __syncthreads();
        if (tid < 128) {
#pragma unroll
            for (int kk = 0; kk < 16; kk++) {
                float4 wv = ld4(&ws[kk * 132 + cg * 4]);
#pragma unroll
                for (int rr = 0; rr < 4; rr++) {
                    float xv = xs[kk * 20 + rg * 4 + rr];
                    acc[rr].x += xv * wv.x; acc[rr].y += xv * wv.y;
                    acc[rr].z += xv * wv.z; acc[rr].w += xv * wv.w;
                }
            }
        }
    }

    if (tid < 128) {
        const float4 b4 = ld4(bin + cg * 4);
#pragma unroll
        for (int rr = 0; rr < 4; rr++) {
            acc[rr].x += b4.x; acc[rr].y += b4.y;
            acc[rr].z += b4.z; acc[rr].w += b4.w;
        }
        // transposed store: g_zin[blk][ uT: c*16+r | vT: 2048 + c*16+r ]
        float* base = g_zin + bid * 4096;
#pragma unroll
        for (int cc = 0; cc < 4; cc++) {
            const int col = cg * 4 + cc;
#pragma unroll
            for (int rp = 0; rp < 2; rp++) {
                const float a0 = FC(acc[rp*2],   cc);
                const float a1 = FC(acc[rp*2+1], cc);
                *(ull*)&base[col * 16 + rg * 4 + rp * 2]        = pk2(a0, a1);
                *(ull*)&base[2048 + col * 16 + rg * 4 + rp * 2] = pk2(tanhf(a0), tanhf(a1));
            }
        }
    }
}

__global__ __launch_bounds__(256) void k_pre(const float* __restrict__ x,
                                             const float* __restrict__ win,
                                             const float* __restrict__ bin,
                                             const float* __restrict__ wblocks,
                                             const float* __restrict__ bblocks)
{
    extern __shared__ float sm[];
    if (blockIdx.x < 8) prep_body(sm, wblocks, bblocks, blockIdx.x);
    else                input_body(sm, x, win, bin, blockIdx.x - 8);
}

// ---------------------------------------------------------------------------
// k_sweep smem layout (floats):
//   zinT 0..4095 | zls 4096..36863 (8 x [uT 2048|vT 2048]) | qT 36864..38911
//   wb 38912..55295 (2x8192) | bb 55296..56319 | Mbs 56320..57343
//   lg 57344..57503 | mbar @57504 (2 x u64)
// ---------------------------------------------------------------------------
#define SW_FLOATS 57508
#define SW_BYTES  (SW_FLOATS * 4)

__device__ __forceinline__ void prefetch_chunk(int c, uint32_t wbB, uint32_t mbar0,
                                               const float* __restrict__ wblocks)
{
    if (c >= NCHUNKS) return;
    const uint32_t dst = wbB + (uint32_t)(c & 1) * 32768u;
    const uint32_t mb  = mbar0 + (uint32_t)(c & 1) * 8u;
    mbar_expect(mb, 32768u);
    if (c >= NCHUNKS - 2) {
        bulk_g2s(dst, g_WT + (c - (NCHUNKS - 2)) * 8192, 32768u, mb);
    } else {
        const int step = c / 6;
        const int l = step & 7;
        const int r = c - step * 6;
        if (r < 4) {
            bulk_g2s(dst,          g_Mt + l * 16384 + r * 4096, 16384u, mb);
            bulk_g2s(dst + 16384u, g_Nt + l * 16384 + r * 4096, 16384u, mb);
        } else {
            bulk_g2s(dst, wblocks + l * 16384 + (r - 4) * 8192, 32768u, mb);
        }
    }
}

__global__ __launch_bounds__(512, 1) void k_sweep(const float* __restrict__ wblocks,
                                                  const float* __restrict__ bblocks,
                                                  const float* __restrict__ wout,
                                                  const float* __restrict__ bout,
                                                  float* __restrict__ out)
{
    extern __shared__ float sm[];
    float* zinT = sm;
    float* zls  = sm + 4096;
    float* qT   = sm + 36864;
    float* wb   = sm + 38912;
    float* bb   = sm + 55296;
    float* Mbs  = sm + 56320;
    float* lg   = sm + 57344;

    const uint32_t smem0 = s2u(sm);
    const uint32_t mbar0 = smem0 + 57504u * 4u;
    const uint32_t wbB   = smem0 + 38912u * 4u;

    const int tid  = threadIdx.x;
    const int wid  = tid >> 5;
    const int lane = tid & 31;
    const int ks   = wid >> 3;              // k-split half
    const int rh   = (wid >> 2) & 1;        // row half
    const int cq   = wid & 3;               // col quarter
    const int rg   = lane >> 4;             // 4-row group within half
    const int cp   = lane & 15;             // colpair within quarter
    const int col2  = cq * 32 + cp * 2;     // lane's first column
    const int rbase = rh * 8 + rg * 4;      // lane's first row
    const int ks16  = ks * 16;
    const int row0  = blockIdx.x * 16;

    for (int idx = tid; idx < 4096; idx += 512) zinT[idx] = g_zin[row0 * 256 + idx];
    for (int idx = tid; idx < 1024; idx += 512) bb[idx] = bblocks[idx];
    for (int idx = tid; idx < 1024; idx += 512) Mbs[idx] = g_Mb[idx];
    if (tid == 0) {
        mbar_init(mbar0, 1);
        mbar_init(mbar0 + 8, 1);
        asm volatile("fence.mbarrier_init.release.cluster;" ::: "memory");
    }
    __syncthreads();
    for (int idx = tid; idx < 32768; idx += 512) zls[idx] = zinT[idx & 4095];
    if (tid == 0) { prefetch_chunk(0, wbB, mbar0, wblocks); prefetch_chunk(1, wbB, mbar0, wblocks); }
    __syncthreads();

    int c = 0;
    for (int it = 0; it < NSTEPS; it++) {
        for (int l = 0; l < NLAYERS; l++) {
            const float* cuT = l ? (zls + (l - 1) * 4096) : zinT;
            const float* cvT = l ? (zls + (l - 1) * 4096 + 2048) : (zinT + 2048);
            float* uTl = zls + l * 4096;
            float* vTl = uTl + 2048;

            // ---- stage qT[k][r] = 10*tanh(uTl[k][r]) + cvT[k][r] (512 thr x 2) ----
#pragma unroll
            for (int s = 0; s < 2; s++) {
                const int ii = tid + s * 512;
                const int base = (ii >> 3) * 16 + (ii & 7) * 2;
                const float2 u2 = *(const float2*)&uTl[base];
                const float2 v2 = *(const float2*)&cvT[base];
                float2 q2;
                q2.x = TANHK * tanhf(u2.x) + v2.x;
                q2.y = TANHK * tanhf(u2.y) + v2.y;
                *(float2*)&qT[base] = q2;
            }
            __syncthreads();

            // ---- u = M*carry + Mb + Ntneg*q  (k-split halves) ----
            ull A0, A1, A2, A3;
            if (ks == 0) {
                const ull mb2 = *(const ull*)&Mbs[l * 128 + col2];
                A0 = mb2; A1 = mb2; A2 = mb2; A3 = mb2;
            } else {
                A0 = A1 = A2 = A3 = 0;
            }
            for (int kc = 0; kc < 4; kc++) {
                mbar_wait(mbar0 + (uint32_t)(c & 1) * 8u, (c >> 1) & 1);
                const float* Mt = wb + (c & 1) * 8192;
                const float* Nt = Mt + 4096;
#pragma unroll
                for (int kk4 = 0; kk4 < 4; kk4++) {
                    const int kb = ks16 + kk4 * 4;
                    const int kg = kc * 32 + kb;
#pragma unroll
                    for (int t = 0; t < 4; t++) {
                        const ull mw = *(const ull*)&Mt[(kb + t) * 128 + col2];
                        const ull nw = *(const ull*)&Nt[(kb + t) * 128 + col2];
                        const float4 cu = ld4(&cuT[(kg + t) * 16 + rbase]);
                        const float4 qq = ld4(&qT [(kg + t) * 16 + rbase]);
                        A0 = fma2(splat(cu.x), mw, A0);
                        A1 = fma2(splat(cu.y), mw, A1);
                        A2 = fma2(splat(cu.z), mw, A2);
                        A3 = fma2(splat(cu.w), mw, A3);
                        A0 = fma2(splat(qq.x), nw, A0);
                        A1 = fma2(splat(qq.y), nw, A1);
                        A2 = fma2(splat(qq.z), nw, A2);
                        A3 = fma2(splat(qq.w), nw, A3);
                    }
                }
                if (kc == 3 && ks == 1) {
                    // store k-half partial before the slot barrier
                    float l0,h0,l1,h1,l2,h2,l3,h3;
                    unpk2(A0,l0,h0); unpk2(A1,l1,h1); unpk2(A2,l2,h2); unpk2(A3,l3,h3);
                    st4(&uTl[col2 * 16 + rbase],       make_float4(l0,l1,l2,l3));
                    st4(&uTl[(col2 + 1) * 16 + rbase], make_float4(h0,h1,h2,h3));
                }
                __syncthreads();
                if (tid == 0) prefetch_chunk(c + 2, wbB, mbar0, wblocks);
                c++;
            }
            if (ks == 0) {
                const float4 p0 = ld4(&uTl[col2 * 16 + rbase]);
                const float4 p1 = ld4(&uTl[(col2 + 1) * 16 + rbase]);
                float l0,h0,l1,h1,l2,h2,l3,h3;
                unpk2(A0,l0,h0); unpk2(A1,l1,h1); unpk2(A2,l2,h2); unpk2(A3,l3,h3);
                st4(&uTl[col2 * 16 + rbase],
                    make_float4(l0+p0.x, l1+p0.y, l2+p0.z, l3+p0.w));
                st4(&uTl[(col2 + 1) * 16 + rbase],
                    make_float4(h0+p1.x, h1+p1.y, h2+p1.z, h3+p1.w));
            }
            __syncthreads();

            // ---- v = (q + 0.1 * u W)/11  (j-split halves) ----
            ull V0 = 0, V1 = 0, V2 = 0, V3 = 0;
            for (int jc = 0; jc < 2; jc++) {
                mbar_wait(mbar0 + (uint32_t)(c & 1) * 8u, (c >> 1) & 1);
                const float* Ws = wb + (c & 1) * 8192;
#pragma unroll
                for (int jj4 = 0; jj4 < 8; jj4++) {
                    const int jb = ks * 32 + jj4 * 4;
                    const int jg = jc * 64 + jb;
#pragma unroll
                    for (int t = 0; t < 4; t++) {
                        const ull w2 = *(const ull*)&Ws[(jb + t) * 128 + col2];
                        const float4 u4 = ld4(&uTl[(jg + t) * 16 + rbase]);
                        V0 = fma2(splat(u4.x), w2, V0);
                        V1 = fma2(splat(u4.y), w2, V1);
                        V2 = fma2(splat(u4.z), w2, V2);
                        V3 = fma2(splat(u4.w), w2, V3);
                    }
                }
                if (jc == 1 && ks == 1) {
                    float l0,h0,l1,h1,l2,h2,l3,h3;
                    unpk2(V0,l0,h0); unpk2(V1,l1,h1); unpk2(V2,l2,h2); unpk2(V3,l3,h3);
                    st4(&vTl[col2 * 16 + rbase],       make_float4(l0,l1,l2,l3));
                    st4(&vTl[(col2 + 1) * 16 + rbase], make_float4(h0,h1,h2,h3));
                }
                __syncthreads();
                if (tid == 0) prefetch_chunk(c + 2, wbB, mbar0, wblocks);
                c++;
            }
            if (ks == 0) {
                const float4 p0 = ld4(&vTl[col2 * 16 + rbase]);
                const float4 p1 = ld4(&vTl[(col2 + 1) * 16 + rbase]);
                const float4 q0 = ld4(&qT[col2 * 16 + rbase]);
                const float4 q1 = ld4(&qT[(col2 + 1) * 16 + rbase]);
                float l0,h0,l1,h1,l2,h2,l3,h3;
                unpk2(V0,l0,h0); unpk2(V1,l1,h1); unpk2(V2,l2,h2); unpk2(V3,l3,h3);
                st4(&vTl[col2 * 16 + rbase], make_float4(
                    (q0.x + DT_A * (l0 + p0.x)) * INVC,
                    (q0.y + DT_A * (l1 + p0.y)) * INVC,
                    (q0.z + DT_A * (l2 + p0.z)) * INVC,
                    (q0.w + DT_A * (l3 + p0.w)) * INVC));
                st4(&vTl[(col2 + 1) * 16 + rbase], make_float4(
                    (q1.x + DT_A * (h0 + p1.x)) * INVC,
                    (q1.y + DT_A * (h1 + p1.y)) * INVC,
                    (q1.z + DT_A * (h2 + p1.z)) * INVC,
                    (q1.w + DT_A * (h3 + p1.w)) * INVC));
            }
            __syncthreads();
        }
    }

    // ---- final block: u_out = zin_u + 0.1*b7 - 0.1*(v7 @ W7^T) -> qT row-major ----
    {
        ull A0 = 0, A1 = 0, A2 = 0, A3 = 0;
        const float* vT7 = zls + 7 * 4096 + 2048;
        float* scr = zls;   // layer-0 uT region, dead now
        for (int ic = 0; ic < 2; ic++) {
            mbar_wait(mbar0 + (uint32_t)(c & 1) * 8u, (c >> 1) & 1);
            const float* Ws = wb + (c & 1) * 8192;   // WT rows ic*64..
#pragma unroll
            for (int ii4 = 0; ii4 < 8; ii4++) {
                const int ib = ks * 32 + ii4 * 4;
                const int ig = ic * 64 + ib;
#pragma unroll
                for (int t = 0; t < 4; t++) {
                    const ull w2 = *(const ull*)&Ws[(ib + t) * 128 + col2];
                    const float4 v4 = ld4(&vT7[(ig + t) * 16 + rbase]);
                    A0 = fma2(splat(v4.x), w2, A0);
                    A1 = fma2(splat(v4.y), w2, A1);
                    A2 = fma2(splat(v4.z), w2, A2);
                    A3 = fma2(splat(v4.w), w2, A3);
                }
            }
            if (ic == 1 && ks == 1) {
                float l0,h0,l1,h1,l2,h2,l3,h3;
                unpk2(A0,l0,h0); unpk2(A1,l1,h1); unpk2(A2,l2,h2); unpk2(A3,l3,h3);
                st4(&scr[col2 * 16 + rbase],       make_float4(l0,l1,l2,l3));
                st4(&scr[(col2 + 1) * 16 + rbase], make_float4(h0,h1,h2,h3));
            }
            __syncthreads();
            c++;
        }
        if (ks == 0) {
            const float4 p0 = ld4(&scr[col2 * 16 + rbase]);
            const float4 p1 = ld4(&scr[(col2 + 1) * 16 + rbase]);
            const float b0 = DT_A * bb[7 * 128 + col2];
            const float b1 = DT_A * bb[7 * 128 + col2 + 1];
            float l0,h0,l1,h1,l2,h2,l3,h3;
            unpk2(A0,l0,h0); unpk2(A1,l1,h1); unpk2(A2,l2,h2); unpk2(A3,l3,h3);
            const float sl[4] = {l0+p0.x, l1+p0.y, l2+p0.z, l3+p0.w};
            const float sh[4] = {h0+p1.x, h1+p1.y, h2+p1.z, h3+p1.w};
#pragma unroll
            for (int i = 0; i < 4; i++) {
                const int r = rbase + i;
                const float r0 = zinT[col2 * 16 + r]       + b0 - DT_A * sl[i];
                const float r1 = zinT[(col2 + 1) * 16 + r] + b1 - DT_A * sh[i];
                *(ull*)&qT[r * 128 + col2] = pk2(r0, r1);
            }
        }
        __syncthreads();
    }

    // ---- logits + softmax (qT holds u_out row-major [r][128]) ----
    for (int t = tid; t < 160; t += 512) {
        const int r = t / 10, o = t % 10;
        const float* ur = qT + r * 128;
        const float* wr = wout + o * 128;
        float a = bout[o];
#pragma unroll 4
        for (int k = 0; k < U; k++) a += ur[k] * wr[k];
        lg[t] = a;
    }
    __syncthreads();
    if (tid < 16) {
        float mx = -1e30f;
#pragma unroll
        for (int o = 0; o < 10; o++) mx = fmaxf(mx, lg[tid * 10 + o]);
        float e[10], s = 0.f;
#pragma unroll
        for (int o = 0; o < 10; o++) { e[o] = expf(lg[tid * 10 + o] - mx); s += e[o]; }
        const float inv = 1.0f / s;
#pragma unroll
        for (int o = 0; o < 10; o++) out[(row0 + tid) * 10 + o] = e[o] * inv;
    }
}

// ---------------------------------------------------------------------------
extern "C" void kernel_launch(void* const* d_in, const int* in_sizes, int n_in,
                              void* d_out, int out_size)
{
    const float* x     = (const float*)d_in[0];
    const float* w_in  = (const float*)d_in[1];
    const float* b_in  = (const float*)d_in[2];
    const float* w_blk = (const float*)d_in[3];
    const float* b_blk = (const float*)d_in[4];
    const float* w_out = (const float*)d_in[5];
    const float* b_out = (const float*)d_in[6];
    float* out = (float*)d_out;

    cudaFuncSetAttribute(k_pre,   cudaFuncAttributeMaxDynamicSharedMemorySize, PREP_SMEM);
    cudaFuncSetAttribute(k_sweep, cudaFuncAttributeMaxDynamicSharedMemorySize, SW_BYTES);

    k_pre  <<<136, 256, PREP_SMEM>>>(x, w_in, b_in, w_blk, b_blk);
    k_sweep<<<128, 512, SW_BYTES>>>(w_blk, b_blk, w_out, b_out, out);
}